// round 3
// baseline (speedup 1.0000x reference)
#include <cuda_runtime.h>
#include <cuda_bf16.h>

#define FULLMASK 0xFFFFFFFFu
#define LOG2E 1.4426950408889634f

__device__ __forceinline__ float ex2f(float x) {
    float r; asm("ex2.approx.f32 %0,%1;" : "=f"(r) : "f"(x)); return r;
}
__device__ __forceinline__ float rcpf(float x) {
    float r; asm("rcp.approx.f32 %0,%1;" : "=f"(r) : "f"(x)); return r;
}
__device__ __forceinline__ float rsqf(float x) {
    float r; asm("rsqrt.approx.f32 %0,%1;" : "=f"(r) : "f"(x)); return r;
}

// Layout: 4 locations per warp, 8 lanes per location.
// t = lane&7, h = t>>2 (row parity), q = t&3 (d-quad).
// Lane holds rows i = 2r+h (r=0..7), columns d = 4q..4q+3 (one float4/row).
// Reductions: xor 1,2 over d-quads; xor 4 over row parity.
// b kept in log2-space; softmax has no max-subtraction (logits bounded ~±45,
// safe in fp32); 1/sum is never materialized: it cancels inside squash:
//   out = v * sq_un / ((s^2 + sq_un) * sqrt(sq_un + eps*s^2))
// where v = unnormalized weighted sum, sq_un = |v|^2, s = sum of exps.
struct Pack {
    float4 P[8];
    float  bb[8];
    float  o0, o1, o2, o3;

    __device__ __forceinline__ void pass() {
        float e[8];
#pragma unroll
        for (int r = 0; r < 8; ++r) e[r] = ex2f(bb[r]);
        float s = ((e[0] + e[1]) + (e[2] + e[3])) +
                  ((e[4] + e[5]) + (e[6] + e[7]));
        s += __shfl_xor_sync(FULLMASK, s, 4);

        float a0 = e[0] * P[0].x, a1 = e[0] * P[0].y;
        float a2 = e[0] * P[0].z, a3 = e[0] * P[0].w;
#pragma unroll
        for (int r = 1; r < 8; ++r) {
            a0 = fmaf(e[r], P[r].x, a0);
            a1 = fmaf(e[r], P[r].y, a1);
            a2 = fmaf(e[r], P[r].z, a2);
            a3 = fmaf(e[r], P[r].w, a3);
        }
        a0 += __shfl_xor_sync(FULLMASK, a0, 4);
        a1 += __shfl_xor_sync(FULLMASK, a1, 4);
        a2 += __shfl_xor_sync(FULLMASK, a2, 4);
        a3 += __shfl_xor_sync(FULLMASK, a3, 4);

        float sq = fmaf(a3, a3, fmaf(a2, a2, fmaf(a1, a1, a0 * a0)));
        sq += __shfl_xor_sync(FULLMASK, sq, 1);
        sq += __shfl_xor_sync(FULLMASK, sq, 2);

        const float s2 = s * s;
        const float f  = sq * rcpf(s2 + sq) * rsqf(fmaf(1e-7f, s2, sq));
        o0 = a0 * f; o1 = a1 * f; o2 = a2 * f; o3 = a3 * f;
    }

    __device__ __forceinline__ void agree() {
#pragma unroll
        for (int r = 0; r < 8; ++r) {
            float p = fmaf(P[r].w, o3,
                      fmaf(P[r].z, o2,
                      fmaf(P[r].y, o1, P[r].x * o0)));
            p += __shfl_xor_sync(FULLMASK, p, 1);
            p += __shfl_xor_sync(FULLMASK, p, 2);
            bb[r] = fmaf(p, LOG2E, bb[r]);
        }
    }
};

__global__ void __launch_bounds__(256, 4) routing_kernel(
    const float* __restrict__ pred,
    const float* __restrict__ b_in,
    const int*   __restrict__ nit,
    float*       __restrict__ out,
    int n_loc, int ohw, int ohw_mask)
{
    const int lane = threadIdx.x & 31;
    const int t = lane & 7;
    const int h = t >> 2;
    const int q = t & 3;
    const unsigned warp_id = blockIdx.x * (blockDim.x >> 5) + (threadIdx.x >> 5);
    const int g = lane >> 3;
    if (warp_id * 4u >= (unsigned)n_loc) return;
    const unsigned loc = warp_id * 4u + g;

    Pack pk;

    // pred tile: 8 coalesced LDG.128 rounds (256 float4 per warp tile)
    const float4* p4 = reinterpret_cast<const float4*>(pred) + (size_t)warp_id * 256;
#pragma unroll
    for (int r = 0; r < 8; ++r)
        pk.P[r] = p4[64 * g + 8 * r + t];

    // logits (log2-space)
    const unsigned bloc = ohw_mask ? (loc & (unsigned)ohw_mask)
                                   : (loc % (unsigned)ohw);
    const float* brow = b_in + (size_t)bloc * 16 + h;
#pragma unroll
    for (int r = 0; r < 8; ++r) pk.bb[r] = __ldg(brow + 2 * r) * LOG2E;

    const int iters = *nit;

    pk.pass();
    if (iters == 3) {
#pragma unroll
        for (int it = 0; it < 3; ++it) { pk.agree(); pk.pass(); }
    } else {
        for (int it = 0; it < iters; ++it) { pk.agree(); pk.pass(); }
    }

    if (h == 0)
        reinterpret_cast<float4*>(out)[(size_t)loc * 4 + q] =
            make_float4(pk.o0, pk.o1, pk.o2, pk.o3);
}

extern "C" void kernel_launch(void* const* d_in, const int* in_sizes, int n_in,
                              void* d_out, int out_size) {
    const float* pred = (const float*)d_in[0];
    const float* b    = (const float*)d_in[1];
    const int*   nit  = (const int*)d_in[2];
    float* out = (float*)d_out;

    const int n_loc = in_sizes[0] / 256;   // B*O*H*W
    const int ohw   = in_sizes[1] / 16;    // O*H*W
    const int ohw_mask = ((ohw & (ohw - 1)) == 0) ? (ohw - 1) : 0;

    const int warps  = (n_loc + 3) / 4;
    const int blocks = (warps + 7) / 8;
    routing_kernel<<<blocks, 256>>>(pred, b, nit, out, n_loc, ohw, ohw_mask);
}

// round 4
// speedup vs baseline: 1.0124x; 1.0124x over previous
#include <cuda_runtime.h>
#include <cuda_bf16.h>

#define FULLMASK 0xFFFFFFFFu
#define LOG2E 1.4426950408889634f

__device__ __forceinline__ float ex2f(float x) {
    float r; asm("ex2.approx.f32 %0,%1;" : "=f"(r) : "f"(x)); return r;
}
__device__ __forceinline__ float rcpf(float x) {
    float r; asm("rcp.approx.f32 %0,%1;" : "=f"(r) : "f"(x)); return r;
}
__device__ __forceinline__ float rsqf(float x) {
    float r; asm("rsqrt.approx.f32 %0,%1;" : "=f"(r) : "f"(x)); return r;
}

// Layout: 4 locations per warp, 8 lanes per location.
// t = lane&7, h = t>>2 (row parity), q = t&3 (d-quad).
// Lane holds rows i = 2r+h (r=0..7), columns d = 4q..4q+3 (one float4/row).
// Reductions: xor 1,2 over d-quads; xor 4 over row parity.
//
// Routing state is kept as UNNORMALIZED exponentials e[r] = 2^(b*log2e):
//   - softmax normalizer 1/s is never materialized; it cancels inside squash:
//       out = v * sq / ((s^2 + sq) * sqrt(sq + eps*s^2)),  v = sum e*P, sq=|v|^2
//   - agreement update b += <p,out>  becomes  e *= 2^(<p,out>*log2e)
// Range: |b| stays < ~45 -> e within 2^+-65, fp32-safe without max-subtract.
__global__ void __launch_bounds__(128, 9) routing_kernel(
    const float* __restrict__ pred,
    const float* __restrict__ b_in,
    const int*   __restrict__ nit,
    float*       __restrict__ out,
    int n_loc, int ohw)
{
    const int lane = threadIdx.x & 31;
    const int t = lane & 7;
    const int h = t >> 2;
    const int q = t & 3;
    const unsigned warp_id = blockIdx.x * (blockDim.x >> 5) + (threadIdx.x >> 5);
    const int g = lane >> 3;
    if (warp_id * 4u >= (unsigned)n_loc) return;
    const unsigned loc = warp_id * 4u + g;

    // pred tile: 8 coalesced LDG.128 rounds (256 float4 per warp tile)
    float4 P[8];
    const float4* p4 = reinterpret_cast<const float4*>(pred) + (size_t)warp_id * 256;
#pragma unroll
    for (int r = 0; r < 8; ++r)
        P[r] = p4[64 * g + 8 * r + t];

    // routing state: e[r] = exp(b) (unnormalized)
    float e[8];
    const float* brow = b_in + (size_t)(loc % (unsigned)ohw) * 16 + h;
#pragma unroll
    for (int r = 0; r < 8; ++r) e[r] = ex2f(__ldg(brow + 2 * r) * LOG2E);

    const int iters = *nit;
    float o0, o1, o2, o3;

    // one routing pass: weighted sum with raw e, deferred-normalizer squash
    auto pass = [&]() {
        float s = ((e[0] + e[1]) + (e[2] + e[3])) +
                  ((e[4] + e[5]) + (e[6] + e[7]));
        s += __shfl_xor_sync(FULLMASK, s, 4);

        float a0 = e[0] * P[0].x, a1 = e[0] * P[0].y;
        float a2 = e[0] * P[0].z, a3 = e[0] * P[0].w;
#pragma unroll
        for (int r = 1; r < 8; ++r) {
            a0 = fmaf(e[r], P[r].x, a0);
            a1 = fmaf(e[r], P[r].y, a1);
            a2 = fmaf(e[r], P[r].z, a2);
            a3 = fmaf(e[r], P[r].w, a3);
        }
        a0 += __shfl_xor_sync(FULLMASK, a0, 4);
        a1 += __shfl_xor_sync(FULLMASK, a1, 4);
        a2 += __shfl_xor_sync(FULLMASK, a2, 4);
        a3 += __shfl_xor_sync(FULLMASK, a3, 4);

        float sq = fmaf(a3, a3, fmaf(a2, a2, fmaf(a1, a1, a0 * a0)));
        sq += __shfl_xor_sync(FULLMASK, sq, 1);
        sq += __shfl_xor_sync(FULLMASK, sq, 2);

        const float s2 = s * s;
        const float f  = sq * rcpf(s2 + sq) * rsqf(fmaf(1e-7f, s2, sq));
        o0 = a0 * f; o1 = a1 * f; o2 = a2 * f; o3 = a3 * f;
    };

    pass();
    for (int it = 0; it < iters; ++it) {
#pragma unroll
        for (int r = 0; r < 8; ++r) {
            float p = fmaf(P[r].w, o3,
                      fmaf(P[r].z, o2,
                      fmaf(P[r].y, o1, P[r].x * o0)));
            p += __shfl_xor_sync(FULLMASK, p, 1);
            p += __shfl_xor_sync(FULLMASK, p, 2);
            e[r] *= ex2f(p * LOG2E);          // b += p in log-space
        }
        pass();
    }

    if (h == 0)
        reinterpret_cast<float4*>(out)[(size_t)loc * 4 + q] =
            make_float4(o0, o1, o2, o3);
}

extern "C" void kernel_launch(void* const* d_in, const int* in_sizes, int n_in,
                              void* d_out, int out_size) {
    const float* pred = (const float*)d_in[0];
    const float* b    = (const float*)d_in[1];
    const int*   nit  = (const int*)d_in[2];
    float* out = (float*)d_out;

    const int n_loc = in_sizes[0] / 256;   // B*O*H*W
    const int ohw   = in_sizes[1] / 16;    // O*H*W

    const int warps  = (n_loc + 3) / 4;    // 4 locations per warp
    const int blocks = (warps + 3) / 4;    // 4 warps per block (128 threads)
    routing_kernel<<<blocks, 128>>>(pred, b, nit, out, n_loc, ohw);
}

// round 5
// speedup vs baseline: 1.0354x; 1.0227x over previous
#include <cuda_runtime.h>
#include <cuda_bf16.h>

#define FULLMASK 0xFFFFFFFFu
#define LOG2E 1.4426950408889634f

using u64 = unsigned long long;

__device__ __forceinline__ u64 fma2(u64 a, u64 b, u64 c) {
    u64 d; asm("fma.rn.f32x2 %0,%1,%2,%3;" : "=l"(d) : "l"(a), "l"(b), "l"(c)); return d;
}
__device__ __forceinline__ u64 mul2(u64 a, u64 b) {
    u64 d; asm("mul.rn.f32x2 %0,%1,%2;" : "=l"(d) : "l"(a), "l"(b)); return d;
}
__device__ __forceinline__ u64 add2(u64 a, u64 b) {
    u64 d; asm("add.rn.f32x2 %0,%1,%2;" : "=l"(d) : "l"(a), "l"(b)); return d;
}
__device__ __forceinline__ u64 bcast2(float v) {
    u64 d; asm("mov.b64 %0,{%1,%1};" : "=l"(d) : "f"(v)); return d;
}
__device__ __forceinline__ float2 unpk(u64 v) {
    float2 r; asm("mov.b64 {%0,%1},%2;" : "=f"(r.x), "=f"(r.y) : "l"(v)); return r;
}
__device__ __forceinline__ float ex2f(float x) {
    float r; asm("ex2.approx.f32 %0,%1;" : "=f"(r) : "f"(x)); return r;
}
__device__ __forceinline__ float rcpf(float x) {
    float r; asm("rcp.approx.f32 %0,%1;" : "=f"(r) : "f"(x)); return r;
}
__device__ __forceinline__ float rsqf(float x) {
    float r; asm("rsqrt.approx.f32 %0,%1;" : "=f"(r) : "f"(x)); return r;
}

union Row { ulonglong2 u; float4 f; };

// Layout: 4 locations per warp, 8 lanes per location.
// t = lane&7, h = t>>2 (row parity), q = t&3 (d-quad).
// Lane holds rows i = 2r+h (r=0..7), cols d = 4q..4q+3 as packed f32x2 pairs.
// Reductions: xor 1,2 over d-quads; xor 4 over row parity.
//
// b kept in log2-space. Softmax normalizer 1/s is NEVER materialized:
//   out = a * sq_un * rcp(s^2 + sq_un) * rsq(sq_un + eps*s^2)
// (a = unnormalized weighted sum, sq_un = |a|^2, s = sum of exps; all powers
// of 1/s cancel). No max-subtraction: logits bounded, fp32-safe.
__global__ void __launch_bounds__(256) routing_kernel(
    const float* __restrict__ pred,
    const float* __restrict__ b_in,
    const int*   __restrict__ nit,
    float*       __restrict__ out,
    int n_loc, int ohw, int ohw_mask)
{
    const int lane = threadIdx.x & 31;
    const int t = lane & 7;
    const int h = t >> 2;
    const int q = t & 3;
    const unsigned warp_id = blockIdx.x * (blockDim.x >> 5) + (threadIdx.x >> 5);
    const int g = lane >> 3;
    if (warp_id * 4u >= (unsigned)n_loc) return;
    const unsigned loc = warp_id * 4u + g;

    // pred tile: 8 coalesced LDG.128 rounds
    const ulonglong2* p4 =
        reinterpret_cast<const ulonglong2*>(pred) + (size_t)warp_id * 256;
    Row P[8];
#pragma unroll
    for (int r = 0; r < 8; ++r)
        P[r].u = p4[64 * g + 8 * r + t];

    // logits (log2-space)
    const unsigned bloc = ohw_mask ? (loc & (unsigned)ohw_mask)
                                   : (loc % (unsigned)ohw);
    float bb[8];
    const float* brow = b_in + (size_t)bloc * 16 + h;
#pragma unroll
    for (int r = 0; r < 8; ++r) bb[r] = __ldg(brow + 2 * r) * LOG2E;

    const int iters = *nit;
    u64 o01, o23;   // squashed output (packed d-quad)

    auto pass = [&]() {
        float e[8];
#pragma unroll
        for (int r = 0; r < 8; ++r) e[r] = ex2f(bb[r]);
        float s = ((e[0] + e[1]) + (e[2] + e[3])) +
                  ((e[4] + e[5]) + (e[6] + e[7]));
        s += __shfl_xor_sync(FULLMASK, s, 4);

        // unnormalized weighted sum over i (packed)
        u64 a01 = 0ull, a23 = 0ull;
#pragma unroll
        for (int r = 0; r < 8; ++r) {
            const u64 ee = bcast2(e[r]);
            a01 = fma2(ee, P[r].u.x, a01);
            a23 = fma2(ee, P[r].u.y, a23);
        }
        a01 = add2(a01, __shfl_xor_sync(FULLMASK, a01, 4));
        a23 = add2(a23, __shfl_xor_sync(FULLMASK, a23, 4));

        // |a|^2 over 16 d
        float2 th = unpk(fma2(a23, a23, mul2(a01, a01)));
        float sq = th.x + th.y;
        sq += __shfl_xor_sync(FULLMASK, sq, 1);
        sq += __shfl_xor_sync(FULLMASK, sq, 2);

        // folded squash: 2 MUFU, 1/s fully cancelled
        const float s2 = s * s;
        const float f  = sq * rcpf(s2 + sq) * rsqf(fmaf(1e-7f, s2, sq));
        const u64 ff = bcast2(f);
        o01 = mul2(a01, ff);
        o23 = mul2(a23, ff);
    };

    pass();
    for (int it = 0; it < iters; ++it) {
#pragma unroll
        for (int r = 0; r < 8; ++r) {
            // packed dot <P_row, out>, horizontal via free half-naming
            float2 d2 = unpk(fma2(P[r].u.y, o23, mul2(P[r].u.x, o01)));
            float p = d2.x + d2.y;
            p += __shfl_xor_sync(FULLMASK, p, 1);
            p += __shfl_xor_sync(FULLMASK, p, 2);
            bb[r] = fmaf(p, LOG2E, bb[r]);
        }
        pass();
    }

    if (h == 0) {
        ulonglong2 res; res.x = o01; res.y = o23;
        reinterpret_cast<ulonglong2*>(out)[(size_t)loc * 4 + q] = res;
    }
}

extern "C" void kernel_launch(void* const* d_in, const int* in_sizes, int n_in,
                              void* d_out, int out_size) {
    const float* pred = (const float*)d_in[0];
    const float* b    = (const float*)d_in[1];
    const int*   nit  = (const int*)d_in[2];
    float* out = (float*)d_out;

    const int n_loc = in_sizes[0] / 256;   // B*O*H*W
    const int ohw   = in_sizes[1] / 16;    // O*H*W
    const int ohw_mask = ((ohw & (ohw - 1)) == 0) ? (ohw - 1) : 0;

    const int warps  = (n_loc + 3) / 4;    // 4 locations per warp
    const int blocks = (warps + 7) / 8;    // 8 warps per block
    routing_kernel<<<blocks, 256>>>(pred, b, nit, out, n_loc, ohw, ohw_mask);
}